// round 13
// baseline (speedup 1.0000x reference)
#include <cuda_runtime.h>
#include <math.h>

#define BDIM   16
#define TDIM   2048
#define FDIM   128
#define LDIM   16
#define LIB    1016
#define NROWS  32768
#define NB     148
#define NT     1024
#define RPB    222          // rows per block in phase E (148*222 >= 32768)

// output offsets (floats)
#define Y_OFF   ((size_t)0)
#define X_OFF   ((size_t)524288)
#define Z_OFF   ((size_t)4718592)
#define J_OFF   ((size_t)5242880)
#define WS_OFF  ((size_t)72351744)
#define WD_OFF  ((size_t)72368000)

// jac regions (float4 units): E 80MB | H 48MB | Yint 64MB | Ytail 64MB
#define E1_END  ((size_t)5242880)
#define H_BEG   ((size_t)5242880)
#define H_END   ((size_t)8388608)
#define YI_BEG  ((size_t)8388608)     // + tile*16384
#define YT_BEG  ((size_t)12582912)
#define YT_END  ((size_t)16777216)

// scratch
__device__ float g_amp[BDIM*LDIM*TDIM];   // [B,L,T]
__device__ float g_ang[BDIM*LDIM*TDIM];   // [B,L,T]
__device__ float g_zt [BDIM*LDIM*TDIM];   // [B,L,T]

// smem layout (floats)
#define S_WENC  0           // 2048   W_enc [16][128]
#define S_WD    2048        // 2048   W_dec [128][16]
#define S_BD    4096        // 128
#define S_BS    4224        // 16
#define S_BE    4240        // 16
#define S_WT    4256        // 16256  W_sindy^T [1016][16]
#define S_COMBO 20512       // 1016
#define S_F     21528       // 6784   [128][53]
#define S_FFT   28312       // 16384  FFT bufs / Y reduce
#define SMEM_FLOATS 44696
#define SMEM_BYTES (SMEM_FLOATS * 4)   // 178784

// ---------------------------------------------------------------------------
// grid barrier: generation counter, release/acquire, replay-safe
// ---------------------------------------------------------------------------
__device__ unsigned int g_bar_count = 0;
__device__ volatile unsigned int g_bar_gen = 0;

__device__ __forceinline__ void grid_sync()
{
    __syncthreads();
    if (threadIdx.x == 0) {
        unsigned int gen = g_bar_gen;
        __threadfence();                               // release prior writes
        if (atomicAdd(&g_bar_count, 1u) == NB - 1) {
            g_bar_count = 0;
            __threadfence();
            g_bar_gen = gen + 1;                       // release barrier
        } else {
            while (g_bar_gen == gen) __nanosleep(32);
        }
        __threadfence();                               // acquire
    }
    __syncthreads();
}

// ---------------------------------------------------------------------------
__global__ __launch_bounds__(NT, 1) void mega_kernel(
    const float* __restrict__ x,       const float* __restrict__ W_enc,
    const float* __restrict__ b_enc,   const float* __restrict__ W_dec,
    const float* __restrict__ b_dec,   const float* __restrict__ W_sindy,
    const float* __restrict__ b_sindy, float* __restrict__ out)
{
    extern __shared__ float smem[];
    const int t = threadIdx.x;
    const int p = blockIdx.x;

    float* sW   = smem + S_WENC;
    float* sWd  = smem + S_WD;
    float* sbd  = smem + S_BD;
    float* sbs  = smem + S_BS;
    float* sbe  = smem + S_BE;
    float* sWt  = smem + S_WT;
    unsigned int* scombo = (unsigned int*)(smem + S_COMBO);
    float* sf   = smem + S_F;
    float* sfft = smem + S_FFT;

    float4* jac4 = (float4*)(out + J_OFF);
    const float4* wsrc = (const float4*)sW;

    // ================= preload =================
    if (t < 512)       ((float4*)sW)[t]        = ((const float4*)W_enc)[t];
    else               ((float4*)sWd)[t - 512] = ((const float4*)W_dec)[t - 512];
    if (t < 128) sbd[t] = b_dec[t];
    if (t < 16)  { sbs[t] = b_sindy[t]; sbe[t] = b_enc[t]; }
    __syncthreads();

    // ================= phase E =================
    if (t < RPB) {
        const int row = p * RPB + t;
        if (row < NROWS) {
            float acc[16];
#pragma unroll
            for (int l = 0; l < 16; l++) acc[l] = sbe[l];
            const float4* xr = (const float4*)(x + (size_t)row * FDIM);
#pragma unroll 4
            for (int c = 0; c < 32; c++) {
                float4 xv = xr[c];
#pragma unroll
                for (int l = 0; l < 16; l++) {
                    float4 wv = ((float4*)sW)[l * 32 + c];
                    acc[l] = fmaf(xv.x, wv.x, acc[l]);
                    acc[l] = fmaf(xv.y, wv.y, acc[l]);
                    acc[l] = fmaf(xv.z, wv.z, acc[l]);
                    acc[l] = fmaf(xv.w, wv.w, acc[l]);
                }
            }
            float4* zo = (float4*)(out + Z_OFF + (size_t)row * LDIM);
            zo[0] = make_float4(acc[0],  acc[1],  acc[2],  acc[3]);
            zo[1] = make_float4(acc[4],  acc[5],  acc[6],  acc[7]);
            zo[2] = make_float4(acc[8],  acc[9],  acc[10], acc[11]);
            zo[3] = make_float4(acc[12], acc[13], acc[14], acc[15]);
            const int b  = row >> 11;
            const int tt = row & 2047;
#pragma unroll
            for (int k = 0; k < 16; k++)
                g_zt[((size_t)(b * 16 + k)) * TDIM + tt] = acc[k];

            // x_hat from live registers
            const float4* wd4 = (const float4*)sWd;
            float4* xo = (float4*)(out + X_OFF + (size_t)row * FDIM);
#pragma unroll 1
            for (int c4 = 0; c4 < 32; c4++) {
                float vv[4];
#pragma unroll
                for (int q = 0; q < 4; q++) {
                    int c = c4 * 4 + q;
                    float4 w0 = wd4[c * 4 + 0], w1 = wd4[c * 4 + 1];
                    float4 w2 = wd4[c * 4 + 2], w3 = wd4[c * 4 + 3];
                    float v = sbd[c];
                    v = fmaf(acc[0],  w0.x, v); v = fmaf(acc[1],  w0.y, v);
                    v = fmaf(acc[2],  w0.z, v); v = fmaf(acc[3],  w0.w, v);
                    v = fmaf(acc[4],  w1.x, v); v = fmaf(acc[5],  w1.y, v);
                    v = fmaf(acc[6],  w1.z, v); v = fmaf(acc[7],  w1.w, v);
                    v = fmaf(acc[8],  w2.x, v); v = fmaf(acc[9],  w2.y, v);
                    v = fmaf(acc[10], w2.z, v); v = fmaf(acc[11], w2.w, v);
                    v = fmaf(acc[12], w3.x, v); v = fmaf(acc[13], w3.y, v);
                    v = fmaf(acc[14], w3.z, v); v = fmaf(acc[15], w3.w, v);
                    vv[q] = v;
                }
                xo[c4] = make_float4(vv[0], vv[1], vv[2], vv[3]);
            }
        }
    } else if (t >= 256 && t < 416) {
        // W_sindy^T into smem
        for (int i = t - 256; i < LDIM * LIB; i += 160) {
            int l = i / LIB;
            int d = i - l * LIB;
            sWt[d * 16 + l] = W_sindy[i];
        }
    } else if (t >= 416 && t < 434) {
        int c = t - 416;
        if (c < 16) {
            int off = 152;
            for (int a = 0; a < c; a++) { int n = 16 - a; off += n * (n + 1) / 2; }
            for (int j = c; j < 16; j++)
                for (int k = j; k < 16; k++)
                    scombo[off++] = (unsigned)c | ((unsigned)j << 8) | ((unsigned)k << 16);
        } else if (c == 16) {
            int d = 0;
            for (int i = 0; i < 16; i++)
                scombo[d++] = (unsigned)i | (49u << 8) | (49u << 16);
            for (int i = 0; i < 16; i++)
                for (int j = i; j < 16; j++)
                    scombo[d++] = (unsigned)i | ((unsigned)j << 8) | (49u << 16);
        } else {
            int d = 968;
            for (int i = 0; i < 48; i++)
                scombo[d++] = (unsigned)i | (49u << 8) | (49u << 16);
        }
    } else if (t >= 512) {
        // jac region E: 80MB streaming
        for (size_t v = (size_t)p * 512 + (t - 512); v < E1_END; v += (size_t)NB * 512)
            __stcs(&jac4[v], wsrc[v & 511]);
    }

    grid_sync();

    // ================= phase H =================
    if (p < 128) {
        const int half = t >> 9;          // 0/1
        const int ht   = t & 511;
        const int seq  = p * 2 + half;
        float2* A = (float2*)sfft + half * 4096;   // src 2048 + dst 2048
        float2* Bb = A + 2048;
        const float* zp = g_zt + (size_t)seq * TDIM;
        for (int i = ht; i < 2048; i += 512) A[i] = make_float2(zp[i], 0.0f);
        __syncthreads();

        float2* src = A;
        float2* dst = Bb;
#pragma unroll 1
        for (int st = 0; st < 11; st++) {
            const int   len  = 1 << st;
            const float coef = -3.14159265358979323846f / (float)len;
            for (int j = ht; j < 1024; j += 512) {
                const int k = j & (len - 1);
                float2 a  = src[j];
                float2 b2 = src[j + 1024];
                float s, c;
                __sincosf(coef * (float)k, &s, &c);
                float2 wb = make_float2(c * b2.x - s * b2.y, c * b2.y + s * b2.x);
                const int base = 2 * (j - k) + k;
                dst[base]       = make_float2(a.x + wb.x, a.y + wb.y);
                dst[base + len] = make_float2(a.x - wb.x, a.y - wb.y);
            }
            __syncthreads();
            float2* tsw = src; src = dst; dst = tsw;
        }
        for (int i = ht; i < 2048; i += 512) {
            float h = (i >= 1 && i < 1024) ? 2.0f : 0.0f;
            src[i].x *= h; src[i].y *= h;
        }
        __syncthreads();
#pragma unroll 1
        for (int st = 0; st < 11; st++) {
            const int   len  = 1 << st;
            const float coef = 3.14159265358979323846f / (float)len;
            for (int j = ht; j < 1024; j += 512) {
                const int k = j & (len - 1);
                float2 a  = src[j];
                float2 b2 = src[j + 1024];
                float s, c;
                __sincosf(coef * (float)k, &s, &c);
                float2 wb = make_float2(c * b2.x - s * b2.y, c * b2.y + s * b2.x);
                const int base = 2 * (j - k) + k;
                dst[base]       = make_float2(a.x + wb.x, a.y + wb.y);
                dst[base + len] = make_float2(a.x - wb.x, a.y - wb.y);
            }
            __syncthreads();
            float2* tsw = src; src = dst; dst = tsw;
        }
        const float scale = 1.0f / 2048.0f;
        const size_t ob = (size_t)seq * TDIM;
        for (int i = ht; i < 2048; i += 512) {
            float re = src[i].x * scale;
            float im = src[i].y * scale;
            g_amp[ob + i] = sqrtf(re * re + im * im);
            g_ang[ob + i] = atan2f(im, re);
        }
    } else {
        if (p == 128) {
            for (int i = t; i < 4064; i += NT)
                ((float4*)(out + WS_OFF))[i] = ((const float4*)W_sindy)[i];
            for (int i = t; i < 512; i += NT)
                ((float4*)(out + WD_OFF))[i] = ((const float4*)W_dec)[i];
        }
        for (size_t v = H_BEG + (size_t)(p - 128) * NT + t; v < H_END; v += (size_t)20 * NT)
            __stcs(&jac4[v], wsrc[v & 511]);
    }

    grid_sync();

    // ================= phase Y =================
    const int w    = t >> 5;
    const int lane = t & 31;
    const int u    = w & 7;          // feature octant
    const int rg   = w >> 3;         // row group 0..3
    float* sred = sfft;              // reuse FFT region

    for (int tile = p; tile < 256; tile += NB) {
        // jac Yint slice for this tile
        {
            size_t base = YI_BEG + (size_t)tile * 16384 + t;
#pragma unroll 4
            for (int k = 0; k < 16; k++) {
                size_t v = base + (size_t)k * NT;
                __stcs(&jac4[v], wsrc[v & 511]);
            }
        }
        __syncthreads();
        // fill f for 128 rows
        {
            int row_l = t >> 3, sl = t & 7;
            int row = tile * 128 + row_l;
            int b = row >> 11, tt = row & 2047;
            float* f = sf + row_l * 53;
#pragma unroll
            for (int m = 0; m < 6; m++) {
                int idx = sl * 6 + m;
                float val;
                if (idx < 16)      val = out[Z_OFF + (size_t)row * LDIM + idx];
                else if (idx < 32) val = g_amp[((size_t)(b * 16 + idx - 16)) * TDIM + tt];
                else               val = g_ang[((size_t)(b * 16 + idx - 32)) * TDIM + tt];
                f[idx] = val;
            }
            if (sl == 0) { f[48] = 1.0f; f[49] = 1.0f; f[50] = 1.0f; f[51] = 1.0f; f[52] = 1.0f; }
        }
        __syncthreads();

        const int row_l = rg * 32 + lane;
        const float* f = sf + row_l * 53;
        unsigned long long A0 = 0, A1 = 0, A2 = 0, A3 = 0,
                           A4 = 0, A5 = 0, A6 = 0, A7 = 0;
        int d = u * 127;
#pragma unroll 2
        for (int s = 0; s < 127; s++, d++) {
            unsigned int c = scombo[d];
            float v = f[c & 63u] * f[(c >> 8) & 63u] * f[(c >> 16) & 63u];
            unsigned long long pk;
            asm("mov.b64 %0,{%1,%1};" : "=l"(pk) : "r"(__float_as_uint(v)));
            const ulonglong2* w2 = (const ulonglong2*)(sWt + (d << 4));
            ulonglong2 p0 = w2[0], p1 = w2[1];
            asm("fma.rn.f32x2 %0,%1,%2,%0;" : "+l"(A0) : "l"(pk), "l"(p0.x));
            asm("fma.rn.f32x2 %0,%1,%2,%0;" : "+l"(A1) : "l"(pk), "l"(p0.y));
            asm("fma.rn.f32x2 %0,%1,%2,%0;" : "+l"(A2) : "l"(pk), "l"(p1.x));
            asm("fma.rn.f32x2 %0,%1,%2,%0;" : "+l"(A3) : "l"(pk), "l"(p1.y));
            ulonglong2 p2 = w2[2], p3 = w2[3];
            asm("fma.rn.f32x2 %0,%1,%2,%0;" : "+l"(A4) : "l"(pk), "l"(p2.x));
            asm("fma.rn.f32x2 %0,%1,%2,%0;" : "+l"(A5) : "l"(pk), "l"(p2.y));
            asm("fma.rn.f32x2 %0,%1,%2,%0;" : "+l"(A6) : "l"(pk), "l"(p3.x));
            asm("fma.rn.f32x2 %0,%1,%2,%0;" : "+l"(A7) : "l"(pk), "l"(p3.y));
        }
        __syncthreads();

#define ADD2(dst, srcv) asm("add.rn.f32x2 %0,%0,%1;" : "+l"(dst) : "l"(srcv))
        float* rb = sred + rg * 2048;
        // round 1
        if (u >= 4) {
            ulonglong2* r2 = (ulonglong2*)(rb + ((u - 4) * 32 + lane) * 16);
            ulonglong2 q;
            q.x = A0; q.y = A1; r2[0] = q;
            q.x = A2; q.y = A3; r2[1] = q;
            q.x = A4; q.y = A5; r2[2] = q;
            q.x = A6; q.y = A7; r2[3] = q;
        }
        __syncthreads();
        if (u < 4) {
            const ulonglong2* r2 = (const ulonglong2*)(rb + (u * 32 + lane) * 16);
            ulonglong2 q0 = r2[0], q1 = r2[1], q2 = r2[2], q3 = r2[3];
            ADD2(A0, q0.x); ADD2(A1, q0.y); ADD2(A2, q1.x); ADD2(A3, q1.y);
            ADD2(A4, q2.x); ADD2(A5, q2.y); ADD2(A6, q3.x); ADD2(A7, q3.y);
        }
        __syncthreads();
        // round 2
        if (u == 2 || u == 3) {
            ulonglong2* r2 = (ulonglong2*)(rb + ((u - 2) * 32 + lane) * 16);
            ulonglong2 q;
            q.x = A0; q.y = A1; r2[0] = q;
            q.x = A2; q.y = A3; r2[1] = q;
            q.x = A4; q.y = A5; r2[2] = q;
            q.x = A6; q.y = A7; r2[3] = q;
        }
        __syncthreads();
        if (u < 2) {
            const ulonglong2* r2 = (const ulonglong2*)(rb + (u * 32 + lane) * 16);
            ulonglong2 q0 = r2[0], q1 = r2[1], q2 = r2[2], q3 = r2[3];
            ADD2(A0, q0.x); ADD2(A1, q0.y); ADD2(A2, q1.x); ADD2(A3, q1.y);
            ADD2(A4, q2.x); ADD2(A5, q2.y); ADD2(A6, q3.x); ADD2(A7, q3.y);
        }
        __syncthreads();
        // round 3
        if (u == 1) {
            ulonglong2* r2 = (ulonglong2*)(rb + lane * 16);
            ulonglong2 q;
            q.x = A0; q.y = A1; r2[0] = q;
            q.x = A2; q.y = A3; r2[1] = q;
            q.x = A4; q.y = A5; r2[2] = q;
            q.x = A6; q.y = A7; r2[3] = q;
        }
        __syncthreads();
        if (u == 0) {
            const ulonglong2* r2 = (const ulonglong2*)(rb + lane * 16);
            ulonglong2 q0 = r2[0], q1 = r2[1], q2 = r2[2], q3 = r2[3];
            ADD2(A0, q0.x); ADD2(A1, q0.y); ADD2(A2, q1.x); ADD2(A3, q1.y);
            ADD2(A4, q2.x); ADD2(A5, q2.y); ADD2(A6, q3.x); ADD2(A7, q3.y);

            const float4* bs4 = (const float4*)sbs;
            float4 b0 = bs4[0], b1 = bs4[1], b2 = bs4[2], b3 = bs4[3];
            float2 v0 = *(float2*)&A0, v1 = *(float2*)&A1;
            float2 v2 = *(float2*)&A2, v3 = *(float2*)&A3;
            float2 v4 = *(float2*)&A4, v5 = *(float2*)&A5;
            float2 v6 = *(float2*)&A6, v7 = *(float2*)&A7;
            const int row = tile * 128 + row_l;
            float4* yo = (float4*)(out + Y_OFF + (size_t)row * LDIM);
            yo[0] = make_float4(v0.x + b0.x, v0.y + b0.y, v1.x + b0.z, v1.y + b0.w);
            yo[1] = make_float4(v2.x + b1.x, v2.y + b1.y, v3.x + b1.z, v3.y + b1.w);
            yo[2] = make_float4(v4.x + b2.x, v4.y + b2.y, v5.x + b2.z, v5.y + b2.w);
            yo[3] = make_float4(v6.x + b3.x, v6.y + b3.y, v7.x + b3.z, v7.y + b3.w);
        }
    }

    // jac tail: drains after kernel end (free)
    for (size_t v = YT_BEG + (size_t)p * NT + t; v < YT_END; v += (size_t)NB * NT)
        __stcs(&jac4[v], wsrc[v & 511]);
}

// ---------------------------------------------------------------------------
extern "C" void kernel_launch(void* const* d_in, const int* in_sizes, int n_in,
                              void* d_out, int out_size)
{
    const float* x       = (const float*)d_in[0];
    const float* W_enc   = (const float*)d_in[1];
    const float* b_enc   = (const float*)d_in[2];
    const float* W_dec   = (const float*)d_in[3];
    const float* b_dec   = (const float*)d_in[4];
    const float* W_sindy = (const float*)d_in[5];
    const float* b_sindy = (const float*)d_in[6];
    float* out = (float*)d_out;

    static int init = 0;
    if (!init) {
        cudaFuncSetAttribute(mega_kernel,
                             cudaFuncAttributeMaxDynamicSharedMemorySize,
                             SMEM_BYTES);
        init = 1;
    }
    mega_kernel<<<NB, NT, SMEM_BYTES>>>(x, W_enc, b_enc, W_dec, b_dec,
                                        W_sindy, b_sindy, out);
}

// round 15
// speedup vs baseline: 1.1103x; 1.1103x over previous
#include <cuda_runtime.h>
#include <math.h>

#define BDIM   16
#define TDIM   2048
#define FDIM   128
#define LDIM   16
#define LIB    1016
#define NROWS  (BDIM*TDIM)          // 32768

// output offsets (floats)
#define Y_OFF   ((size_t)0)
#define X_OFF   ((size_t)524288)
#define Z_OFF   ((size_t)4718592)
#define J_OFF   ((size_t)5242880)
#define WS_OFF  ((size_t)72351744)
#define WD_OFF  ((size_t)72368000)

// jac float4 regions: encoder 72MiB | hilbert 104MiB | fused 80MiB
#define JAC_E_BEG ((size_t)0)
#define JAC_E_LEN ((size_t)4718592)    // 288 blocks * 256 thr * 64
#define JAC_H_BEG ((size_t)4718592)
#define JAC_H_LEN ((size_t)6815744)    // 128 blocks * 1024 thr * 52
#define JAC_F_BEG ((size_t)11534336)
#define JAC_F_LEN ((size_t)5242880)    // 512 blocks * 10240

// scratch
__device__ float g_amp[BDIM*LDIM*TDIM];          // [B,L,T]
__device__ float g_ang[BDIM*LDIM*TDIM];          // [B,L,T]
__device__ float g_zt [BDIM*LDIM*TDIM];          // [B,L,T]
__device__ __align__(16) float g_Wt[LIB*LDIM];   // W_sindy transposed [d][l]
__device__ unsigned int g_combo[LIB];            // packed (i | j<<8 | k<<16); 49 -> 1.0

// fused smem (floats): Wt 16256 | f 1696 | combo 1016 = 18968 fl = 75872 B, 3/SM
// reduce buffer (1024 fl) reuses the f region ONLY (combo survives for tile 2)
#define SM_F      16256
#define SM_COMBO  (16256 + 1696)
#define SM_RED    16256
#define FUSED_SMEM_BYTES ((16256 + 1696 + 1016) * 4)

// ---------------------------------------------------------------------------
__device__ __forceinline__ void jac_store(float* __restrict__ out,
                                          const float4* __restrict__ tile,
                                          size_t region_beg, size_t region_len,
                                          int jb, int nblk, int tid, int nthr)
{
    float4* jac4 = (float4*)(out + J_OFF);
    const size_t stride = (size_t)nblk * nthr;
    for (size_t v = (size_t)jb * nthr + tid; v < region_len; v += stride) {
        size_t gidx = region_beg + v;
        __stcs(&jac4[gidx], tile[gidx & 511]);
    }
}

// ---------------------------------------------------------------------------
// K1: encoder. blocks [0,128): z = x @ W_enc^T + b_enc, ONE thread per row.
//     block 128: transpose W_sindy -> g_Wt + combo table.
//     blocks [129,417): jac region E (72 MiB).
// ---------------------------------------------------------------------------
__global__ __launch_bounds__(256) void encoder_kernel(
    const float* __restrict__ x, const float* __restrict__ W_enc,
    const float* __restrict__ b_enc, const float* __restrict__ W_sindy,
    float* __restrict__ z_out, float* __restrict__ out)
{
    __shared__ float4 sW[512];
    __shared__ float  sb[16];
    const int tid = threadIdx.x;
    const int bb  = blockIdx.x;

    if (bb == 128) {
        for (int i = tid; i < LDIM * LIB; i += 256) {
            int l = i / LIB;
            int d = i - l * LIB;
            g_Wt[d * 16 + l] = W_sindy[i];
        }
        if (tid < 16) {
            int off = 152;
            for (int a = 0; a < tid; a++) { int n = 16 - a; off += n * (n + 1) / 2; }
            for (int j = tid; j < 16; j++)
                for (int k = j; k < 16; k++)
                    g_combo[off++] = (unsigned)tid | ((unsigned)j << 8) | ((unsigned)k << 16);
        } else if (tid == 16) {
            int d = 0;
            for (int i = 0; i < 16; i++)
                g_combo[d++] = (unsigned)i | (49u << 8) | (49u << 16);
            for (int i = 0; i < 16; i++)
                for (int j = i; j < 16; j++)
                    g_combo[d++] = (unsigned)i | ((unsigned)j << 8) | (49u << 16);
        } else if (tid == 17) {
            int d = 968;
            for (int i = 0; i < 48; i++)
                g_combo[d++] = (unsigned)i | (49u << 8) | (49u << 16);
        }
        return;
    }

    for (int i = tid; i < 512; i += 256) sW[i] = ((const float4*)W_enc)[i];

    if (bb >= 129) {
        __syncthreads();
        jac_store(out, sW, JAC_E_BEG, JAC_E_LEN, bb - 129, 288, tid, 256);
        return;
    }

    if (tid < 16) sb[tid] = b_enc[tid];
    __syncthreads();

    const int row = bb * 256 + tid;
    const float4* xr = (const float4*)(x + (size_t)row * FDIM);

    float acc[16];
#pragma unroll
    for (int l = 0; l < 16; l++) acc[l] = sb[l];

#pragma unroll 4
    for (int c = 0; c < 32; c++) {
        float4 xv = xr[c];
#pragma unroll
        for (int l = 0; l < 16; l++) {
            float4 wv = sW[l * 32 + c];
            acc[l] = fmaf(xv.x, wv.x, acc[l]);
            acc[l] = fmaf(xv.y, wv.y, acc[l]);
            acc[l] = fmaf(xv.z, wv.z, acc[l]);
            acc[l] = fmaf(xv.w, wv.w, acc[l]);
        }
    }
    float4* zo = (float4*)(z_out + (size_t)row * LDIM);
    zo[0] = make_float4(acc[0],  acc[1],  acc[2],  acc[3]);
    zo[1] = make_float4(acc[4],  acc[5],  acc[6],  acc[7]);
    zo[2] = make_float4(acc[8],  acc[9],  acc[10], acc[11]);
    zo[3] = make_float4(acc[12], acc[13], acc[14], acc[15]);

    const int b = row >> 11;
    const int t = row & 2047;
#pragma unroll
    for (int k = 0; k < 16; k++)
        g_zt[((size_t)(b * 16 + k)) * TDIM + t] = acc[k];
}

// ---------------------------------------------------------------------------
// K2: hilbert+X. blocks [0,256): 2048-pt FFT->filter->iFFT.
//     blocks [256,384): jac region H (104 MiB).
//     blocks [384,512): X role — x_hat = z @ W_dec^T + b_dec.
// ---------------------------------------------------------------------------
__global__ __launch_bounds__(1024) void hilbert_kernel(
    const float* __restrict__ W_enc,
    const float* __restrict__ W_dec, const float* __restrict__ b_dec,
    const float* __restrict__ z, float* __restrict__ out)
{
    __shared__ float2 bufA[2048];
    __shared__ float2 bufB[2048];
    const int tid = threadIdx.x;
    const int bb  = blockIdx.x;

    if (bb >= 384) {
        // ---- X role: rows [g*256, +256), 8 row-groups x 128 cols ----
        const int g   = bb - 384;
        const int col = tid & 127;
        const int rg  = tid >> 7;         // 0..7
        const float4* wd = (const float4*)W_dec;
        float4 w0 = wd[col * 4 + 0];
        float4 w1 = wd[col * 4 + 1];
        float4 w2 = wd[col * 4 + 2];
        float4 w3 = wd[col * 4 + 3];
        float  bd = b_dec[col];
        const int rbase = g * 256 + rg * 32;
#pragma unroll 4
        for (int rr = 0; rr < 32; rr++) {
            const float4* zr = (const float4*)(z + (size_t)(rbase + rr) * LDIM);
            float4 z0 = __ldg(zr + 0), z1 = __ldg(zr + 1);
            float4 z2 = __ldg(zr + 2), z3 = __ldg(zr + 3);
            float v = bd;
            v = fmaf(z0.x, w0.x, v); v = fmaf(z0.y, w0.y, v);
            v = fmaf(z0.z, w0.z, v); v = fmaf(z0.w, w0.w, v);
            v = fmaf(z1.x, w1.x, v); v = fmaf(z1.y, w1.y, v);
            v = fmaf(z1.z, w1.z, v); v = fmaf(z1.w, w1.w, v);
            v = fmaf(z2.x, w2.x, v); v = fmaf(z2.y, w2.y, v);
            v = fmaf(z2.z, w2.z, v); v = fmaf(z2.w, w2.w, v);
            v = fmaf(z3.x, w3.x, v); v = fmaf(z3.y, w3.y, v);
            v = fmaf(z3.z, w3.z, v); v = fmaf(z3.w, w3.w, v);
            out[X_OFF + (size_t)(rbase + rr) * FDIM + col] = v;
        }
        return;
    }

    if (bb >= 256) {
        float4* tile = (float4*)bufA;
        const float4* we4 = (const float4*)W_enc;
        if (tid < 512) tile[tid] = we4[tid];
        __syncthreads();
        jac_store(out, tile, JAC_H_BEG, JAC_H_LEN, bb - 256, 128, tid, 1024);
        return;
    }

    const int seq = bb;
    const float* zp = g_zt + (size_t)seq * TDIM;
    bufA[tid]        = make_float2(zp[tid], 0.0f);
    bufA[tid + 1024] = make_float2(zp[tid + 1024], 0.0f);
    __syncthreads();

    float2* src = bufA;
    float2* dst = bufB;

#pragma unroll 1
    for (int p = 0; p < 11; p++) {                 // forward FFT
        const int   len  = 1 << p;
        const float coef = -3.14159265358979323846f / (float)len;
        const int j = tid;
        const int k = j & (len - 1);
        float2 a  = src[j];
        float2 b2 = src[j + 1024];
        float s, c;
        __sincosf(coef * (float)k, &s, &c);
        float2 wb = make_float2(c * b2.x - s * b2.y, c * b2.y + s * b2.x);
        const int base = 2 * (j - k) + k;
        dst[base]       = make_float2(a.x + wb.x, a.y + wb.y);
        dst[base + len] = make_float2(a.x - wb.x, a.y - wb.y);
        __syncthreads();
        float2* tsw = src; src = dst; dst = tsw;
    }

    {   // H filter: H[0]=0, H[1..1023]=2, H[1024..2047]=0
        float h0 = (tid >= 1) ? 2.0f : 0.0f;
        src[tid].x *= h0;  src[tid].y *= h0;
        src[tid + 1024].x = 0.0f; src[tid + 1024].y = 0.0f;
    }
    __syncthreads();

#pragma unroll 1
    for (int p = 0; p < 11; p++) {                 // inverse FFT
        const int   len  = 1 << p;
        const float coef = 3.14159265358979323846f / (float)len;
        const int j = tid;
        const int k = j & (len - 1);
        float2 a  = src[j];
        float2 b2 = src[j + 1024];
        float s, c;
        __sincosf(coef * (float)k, &s, &c);
        float2 wb = make_float2(c * b2.x - s * b2.y, c * b2.y + s * b2.x);
        const int base = 2 * (j - k) + k;
        dst[base]       = make_float2(a.x + wb.x, a.y + wb.y);
        dst[base + len] = make_float2(a.x - wb.x, a.y - wb.y);
        __syncthreads();
        float2* tsw = src; src = dst; dst = tsw;
    }

    const float scale = 1.0f / 2048.0f;
    const size_t ob = (size_t)seq * TDIM;
#pragma unroll
    for (int it = 0; it < 2; it++) {
        int t = tid + it * 1024;
        float re = src[t].x * scale;
        float im = src[t].y * scale;
        g_amp[ob + t] = sqrtf(re * re + im * im);
        g_ang[ob + t] = atan2f(im, re);
    }
}

// ---------------------------------------------------------------------------
// K3: fused (Y + jac). 512 blocks x 256 thr, 3/SM; block bb owns TWO 32-row
// tiles (2*bb, 2*bb+1) and jac slice [bb*10240, +10240). Wt/combo loaded once.
// Y: warp = feature octant (broadcast weights, f32x2 FMA), lane = row.
// Reduce: 4-round tree in a 1024-float buffer inside the dead f region
// (combo stays intact for tile 2). Block 512: copy W_sindy, W_dec.
// ---------------------------------------------------------------------------
#define ADD2(dst, srcv) asm("add.rn.f32x2 %0,%0,%1;" : "+l"(dst) : "l"(srcv))

__global__ __launch_bounds__(256, 3) void fused_kernel(
    const float* __restrict__ W_enc,
    const float* __restrict__ W_dec,
    const float* __restrict__ W_sindy, const float* __restrict__ b_sindy,
    const float* __restrict__ z,       // z region of output blob [B,T,L]
    float* __restrict__ out)
{
    extern __shared__ float smem[];
    const int tid = threadIdx.x;
    const int bb  = blockIdx.x;

    if (bb == 512) {
        const float4* ws4 = (const float4*)W_sindy;
        float4* o1 = (float4*)(out + WS_OFF);
        for (int i = tid; i < (LDIM * LIB) / 4; i += 256) o1[i] = ws4[i];
        const float4* wd4 = (const float4*)W_dec;
        float4* o2 = (float4*)(out + WD_OFF);
        for (int i = tid; i < (FDIM * LDIM) / 4; i += 256) o2[i] = wd4[i];
        return;
    }

    // ---- (1) jac slice: 10240 float4 per block (40/thread), fire-and-forget
    {
        const float4* we4 = (const float4*)W_enc;
        float4* jac4 = (float4*)(out + J_OFF);
        const size_t vbase = JAC_F_BEG + (size_t)bb * 10240 + tid;
#pragma unroll 8
        for (int k = 0; k < 40; k++) {
            size_t v = vbase + (size_t)k * 256;
            __stcs(&jac4[v], __ldg(&we4[v & 511]));
        }
    }

    // ---- (2) Wt + combo fill (ONCE per block) ----
    float* s_Wt = smem;                       // [1016][16]
    float* s_f  = smem + SM_F;                // [32][53]
    unsigned int* s_combo = (unsigned int*)(smem + SM_COMBO);
    {
        const float4* wt4 = (const float4*)g_Wt;
        float4* d4 = (float4*)s_Wt;
        for (int i = tid; i < (LIB * LDIM) / 4; i += 256) d4[i] = wt4[i];
        for (int i = tid; i < LIB; i += 256) s_combo[i] = g_combo[i];
    }

    const int u    = tid >> 5;        // warp id = feature octant
    const int lane = tid & 31;        // row within tile
    float* s_red = smem + SM_RED;     // 1024 floats, overlaps f only

    const float4* bs4 = (const float4*)b_sindy;
    float4 b0 = __ldg(bs4 + 0), b1 = __ldg(bs4 + 1);
    float4 b2 = __ldg(bs4 + 2), b3 = __ldg(bs4 + 3);

    for (int half = 0; half < 2; half++) {
        const int tile = bb * 2 + half;

        // ---- f fill for this tile's 32 rows ----
        {
            const int row_l = tid >> 3;       // 0..31
            const int sl    = tid & 7;        // 0..7
            const int row   = tile * 32 + row_l;
            const int b     = row >> 11;
            const int tt    = row & 2047;
            float* f = s_f + row_l * 53;
#pragma unroll
            for (int m = 0; m < 6; m++) {
                int idx = sl * 6 + m;         // 0..47
                float val;
                if (idx < 16)      val = z[(size_t)row * LDIM + idx];
                else if (idx < 32) val = g_amp[((size_t)(b * 16 + idx - 16)) * TDIM + tt];
                else               val = g_ang[((size_t)(b * 16 + idx - 32)) * TDIM + tt];
                f[idx] = val;
            }
            if (sl == 0) { f[48] = 1.0f; f[49] = 1.0f; f[50] = 1.0f; f[51] = 1.0f; f[52] = 1.0f; }
        }
        __syncthreads();

        // ---- Y: warp u walks d = u*127..u*127+126, packed f32x2 FMA ----
        const int row = tile * 32 + lane;
        const float* f = s_f + lane * 53;
        unsigned long long A0 = 0, A1 = 0, A2 = 0, A3 = 0,
                           A4 = 0, A5 = 0, A6 = 0, A7 = 0;
        int d = u * 127;
#pragma unroll 2
        for (int s = 0; s < 127; s++, d++) {
            unsigned int c = s_combo[d];                       // broadcast
            float v = f[c & 63u] * f[(c >> 8) & 63u] * f[(c >> 16) & 63u];
            unsigned long long pk;
            asm("mov.b64 %0,{%1,%1};" : "=l"(pk) : "r"(__float_as_uint(v)));
            const ulonglong2* w2 = (const ulonglong2*)(s_Wt + (d << 4)); // broadcast
            ulonglong2 p0 = w2[0], p1 = w2[1];
            asm("fma.rn.f32x2 %0,%1,%2,%0;" : "+l"(A0) : "l"(pk), "l"(p0.x));
            asm("fma.rn.f32x2 %0,%1,%2,%0;" : "+l"(A1) : "l"(pk), "l"(p0.y));
            asm("fma.rn.f32x2 %0,%1,%2,%0;" : "+l"(A2) : "l"(pk), "l"(p1.x));
            asm("fma.rn.f32x2 %0,%1,%2,%0;" : "+l"(A3) : "l"(pk), "l"(p1.y));
            ulonglong2 p2 = w2[2], p3 = w2[3];
            asm("fma.rn.f32x2 %0,%1,%2,%0;" : "+l"(A4) : "l"(pk), "l"(p2.x));
            asm("fma.rn.f32x2 %0,%1,%2,%0;" : "+l"(A5) : "l"(pk), "l"(p2.y));
            asm("fma.rn.f32x2 %0,%1,%2,%0;" : "+l"(A6) : "l"(pk), "l"(p3.x));
            asm("fma.rn.f32x2 %0,%1,%2,%0;" : "+l"(A7) : "l"(pk), "l"(p3.y));
        }
        __syncthreads();    // f dead; its region becomes the reduce buffer

        // ---- 4-round reduce (buffer = 1024 floats; combo untouched) ----
        // R1: u4,u5 store; u0,u1 add        -> A(0)=0+4, A(1)=1+5
        if (u == 4 || u == 5) {
            ulonglong2* r2 = (ulonglong2*)(s_red + ((u - 4) * 32 + lane) * 16);
            ulonglong2 q;
            q.x = A0; q.y = A1; r2[0] = q;
            q.x = A2; q.y = A3; r2[1] = q;
            q.x = A4; q.y = A5; r2[2] = q;
            q.x = A6; q.y = A7; r2[3] = q;
        }
        __syncthreads();
        if (u < 2) {
            const ulonglong2* r2 = (const ulonglong2*)(s_red + (u * 32 + lane) * 16);
            ulonglong2 q0 = r2[0], q1 = r2[1], q2 = r2[2], q3 = r2[3];
            ADD2(A0, q0.x); ADD2(A1, q0.y); ADD2(A2, q1.x); ADD2(A3, q1.y);
            ADD2(A4, q2.x); ADD2(A5, q2.y); ADD2(A6, q3.x); ADD2(A7, q3.y);
        }
        __syncthreads();
        // R2: u6,u7 store; u2,u3 add        -> A(2)=2+6, A(3)=3+7
        if (u == 6 || u == 7) {
            ulonglong2* r2 = (ulonglong2*)(s_red + ((u - 6) * 32 + lane) * 16);
            ulonglong2 q;
            q.x = A0; q.y = A1; r2[0] = q;
            q.x = A2; q.y = A3; r2[1] = q;
            q.x = A4; q.y = A5; r2[2] = q;
            q.x = A6; q.y = A7; r2[3] = q;
        }
        __syncthreads();
        if (u == 2 || u == 3) {
            const ulonglong2* r2 = (const ulonglong2*)(s_red + ((u - 2) * 32 + lane) * 16);
            ulonglong2 q0 = r2[0], q1 = r2[1], q2 = r2[2], q3 = r2[3];
            ADD2(A0, q0.x); ADD2(A1, q0.y); ADD2(A2, q1.x); ADD2(A3, q1.y);
            ADD2(A4, q2.x); ADD2(A5, q2.y); ADD2(A6, q3.x); ADD2(A7, q3.y);
        }
        __syncthreads();
        // R3: u2,u3 store; u0,u1 add        -> A(0)=0+2+4+6, A(1)=1+3+5+7
        if (u == 2 || u == 3) {
            ulonglong2* r2 = (ulonglong2*)(s_red + ((u - 2) * 32 + lane) * 16);
            ulonglong2 q;
            q.x = A0; q.y = A1; r2[0] = q;
            q.x = A2; q.y = A3; r2[1] = q;
            q.x = A4; q.y = A5; r2[2] = q;
            q.x = A6; q.y = A7; r2[3] = q;
        }
        __syncthreads();
        if (u < 2) {
            const ulonglong2* r2 = (const ulonglong2*)(s_red + (u * 32 + lane) * 16);
            ulonglong2 q0 = r2[0], q1 = r2[1], q2 = r2[2], q3 = r2[3];
            ADD2(A0, q0.x); ADD2(A1, q0.y); ADD2(A2, q1.x); ADD2(A3, q1.y);
            ADD2(A4, q2.x); ADD2(A5, q2.y); ADD2(A6, q3.x); ADD2(A7, q3.y);
        }
        __syncthreads();
        // R4: u1 stores; u0 adds + bias + output
        if (u == 1) {
            ulonglong2* r2 = (ulonglong2*)(s_red + lane * 16);
            ulonglong2 q;
            q.x = A0; q.y = A1; r2[0] = q;
            q.x = A2; q.y = A3; r2[1] = q;
            q.x = A4; q.y = A5; r2[2] = q;
            q.x = A6; q.y = A7; r2[3] = q;
        }
        __syncthreads();
        if (u == 0) {
            const ulonglong2* r2 = (const ulonglong2*)(s_red + lane * 16);
            ulonglong2 q0 = r2[0], q1 = r2[1], q2 = r2[2], q3 = r2[3];
            ADD2(A0, q0.x); ADD2(A1, q0.y); ADD2(A2, q1.x); ADD2(A3, q1.y);
            ADD2(A4, q2.x); ADD2(A5, q2.y); ADD2(A6, q3.x); ADD2(A7, q3.y);

            float2 v0 = *(float2*)&A0, v1 = *(float2*)&A1;
            float2 v2 = *(float2*)&A2, v3 = *(float2*)&A3;
            float2 v4 = *(float2*)&A4, v5 = *(float2*)&A5;
            float2 v6 = *(float2*)&A6, v7 = *(float2*)&A7;
            float4* yo = (float4*)(out + Y_OFF + (size_t)row * LDIM);
            yo[0] = make_float4(v0.x + b0.x, v0.y + b0.y, v1.x + b0.z, v1.y + b0.w);
            yo[1] = make_float4(v2.x + b1.x, v2.y + b1.y, v3.x + b1.z, v3.y + b1.w);
            yo[2] = make_float4(v4.x + b2.x, v4.y + b2.y, v5.x + b2.z, v5.y + b2.w);
            yo[3] = make_float4(v6.x + b3.x, v6.y + b3.y, v7.x + b3.z, v7.y + b3.w);
        }
        __syncthreads();   // protect s_red/f region before next tile's f fill
    }
}

// ---------------------------------------------------------------------------
extern "C" void kernel_launch(void* const* d_in, const int* in_sizes, int n_in,
                              void* d_out, int out_size)
{
    const float* x       = (const float*)d_in[0];
    const float* W_enc   = (const float*)d_in[1];
    const float* b_enc   = (const float*)d_in[2];
    const float* W_dec   = (const float*)d_in[3];
    const float* b_dec   = (const float*)d_in[4];
    const float* W_sindy = (const float*)d_in[5];
    const float* b_sindy = (const float*)d_in[6];
    float* out = (float*)d_out;

    float* z_out = out + Z_OFF;

    encoder_kernel<<<417, 256>>>(x, W_enc, b_enc, W_sindy, z_out, out);
    hilbert_kernel<<<512, 1024>>>(W_enc, W_dec, b_dec, z_out, out);

    static int smem_set = 0;
    if (!smem_set) {
        cudaFuncSetAttribute(fused_kernel,
                             cudaFuncAttributeMaxDynamicSharedMemorySize,
                             FUSED_SMEM_BYTES);
        smem_set = 1;
    }
    fused_kernel<<<513, 256, FUSED_SMEM_BYTES>>>(
        W_enc, W_dec, W_sindy, b_sindy, z_out, out);
}

// round 16
// speedup vs baseline: 1.1844x; 1.0667x over previous
#include <cuda_runtime.h>
#include <math.h>

#define BDIM   16
#define TDIM   2048
#define FDIM   128
#define LDIM   16
#define LIB    1016
#define NROWS  (BDIM*TDIM)          // 32768

// output offsets (floats)
#define Y_OFF   ((size_t)0)
#define X_OFF   ((size_t)524288)
#define Z_OFF   ((size_t)4718592)
#define J_OFF   ((size_t)5242880)
#define WS_OFF  ((size_t)72351744)
#define WD_OFF  ((size_t)72368000)

// jac float4 regions: encoder 48MiB | hilbert 108MiB | fused 100MiB
// E: 384 blocks * 256 thr * 32   = 3145728
// H: 128 blocks * 1024 thr * 54  = 7077888
// F: 1024 blocks * 256 thr * 25  = 6553600     (sum = 16777216 ✓)
#define JAC_E_BEG ((size_t)0)
#define JAC_E_LEN ((size_t)3145728)
#define JAC_H_BEG ((size_t)3145728)
#define JAC_H_LEN ((size_t)7077888)
#define JAC_F_BEG ((size_t)10223616)
#define JAC_F_LEN ((size_t)6553600)

// scratch
__device__ float g_amp[BDIM*LDIM*TDIM];          // [B,L,T]
__device__ float g_ang[BDIM*LDIM*TDIM];          // [B,L,T]
__device__ float g_zt [BDIM*LDIM*TDIM];          // [B,L,T]
__device__ __align__(16) float g_Wt[LIB*LDIM];   // W_sindy transposed [d][l]
__device__ unsigned int g_combo[LIB];            // packed (i | j<<8 | k<<16); 49 -> 1.0

// fused smem (floats): Wt 16256 | f 1696 | combo 1016 = 18968 fl = 75872 B, 3/SM
// reduce buffer reuses f+combo region (both dead after the single Y loop)
#define SM_F      16256
#define SM_COMBO  (16256 + 1696)
#define SM_RED    16256
#define FUSED_SMEM_BYTES ((16256 + 1696 + 1016) * 4)

// ---------------------------------------------------------------------------
__device__ __forceinline__ void jac_store(float* __restrict__ out,
                                          const float4* __restrict__ tile,
                                          size_t region_beg, size_t region_len,
                                          int jb, int nblk, int tid, int nthr)
{
    float4* jac4 = (float4*)(out + J_OFF);
    const size_t stride = (size_t)nblk * nthr;
    for (size_t v = (size_t)jb * nthr + tid; v < region_len; v += stride) {
        size_t gidx = region_beg + v;
        __stcs(&jac4[gidx], tile[gidx & 511]);
    }
}

// ---------------------------------------------------------------------------
// K1: encoder. blocks [0,128): z = x @ W_enc^T + b_enc, ONE thread per row.
//     block 128: transpose W_sindy -> g_Wt + combo table.
//     blocks [129,513): jac region E (48 MiB over 384 blocks -> drain < compute).
// ---------------------------------------------------------------------------
__global__ __launch_bounds__(256) void encoder_kernel(
    const float* __restrict__ x, const float* __restrict__ W_enc,
    const float* __restrict__ b_enc, const float* __restrict__ W_sindy,
    float* __restrict__ z_out, float* __restrict__ out)
{
    __shared__ float4 sW[512];
    __shared__ float  sb[16];
    const int tid = threadIdx.x;
    const int bb  = blockIdx.x;

    if (bb == 128) {
        for (int i = tid; i < LDIM * LIB; i += 256) {
            int l = i / LIB;
            int d = i - l * LIB;
            g_Wt[d * 16 + l] = W_sindy[i];
        }
        if (tid < 16) {
            int off = 152;
            for (int a = 0; a < tid; a++) { int n = 16 - a; off += n * (n + 1) / 2; }
            for (int j = tid; j < 16; j++)
                for (int k = j; k < 16; k++)
                    g_combo[off++] = (unsigned)tid | ((unsigned)j << 8) | ((unsigned)k << 16);
        } else if (tid == 16) {
            int d = 0;
            for (int i = 0; i < 16; i++)
                g_combo[d++] = (unsigned)i | (49u << 8) | (49u << 16);
            for (int i = 0; i < 16; i++)
                for (int j = i; j < 16; j++)
                    g_combo[d++] = (unsigned)i | ((unsigned)j << 8) | (49u << 16);
        } else if (tid == 17) {
            int d = 968;
            for (int i = 0; i < 48; i++)
                g_combo[d++] = (unsigned)i | (49u << 8) | (49u << 16);
        }
        return;
    }

    for (int i = tid; i < 512; i += 256) sW[i] = ((const float4*)W_enc)[i];

    if (bb >= 129) {
        __syncthreads();
        jac_store(out, sW, JAC_E_BEG, JAC_E_LEN, bb - 129, 384, tid, 256);
        return;
    }

    if (tid < 16) sb[tid] = b_enc[tid];
    __syncthreads();

    const int row = bb * 256 + tid;
    const float4* xr = (const float4*)(x + (size_t)row * FDIM);

    float acc[16];
#pragma unroll
    for (int l = 0; l < 16; l++) acc[l] = sb[l];

#pragma unroll 4
    for (int c = 0; c < 32; c++) {
        float4 xv = xr[c];
#pragma unroll
        for (int l = 0; l < 16; l++) {
            float4 wv = sW[l * 32 + c];
            acc[l] = fmaf(xv.x, wv.x, acc[l]);
            acc[l] = fmaf(xv.y, wv.y, acc[l]);
            acc[l] = fmaf(xv.z, wv.z, acc[l]);
            acc[l] = fmaf(xv.w, wv.w, acc[l]);
        }
    }
    float4* zo = (float4*)(z_out + (size_t)row * LDIM);
    zo[0] = make_float4(acc[0],  acc[1],  acc[2],  acc[3]);
    zo[1] = make_float4(acc[4],  acc[5],  acc[6],  acc[7]);
    zo[2] = make_float4(acc[8],  acc[9],  acc[10], acc[11]);
    zo[3] = make_float4(acc[12], acc[13], acc[14], acc[15]);

    const int b = row >> 11;
    const int t = row & 2047;
#pragma unroll
    for (int k = 0; k < 16; k++)
        g_zt[((size_t)(b * 16 + k)) * TDIM + t] = acc[k];
}

// ---------------------------------------------------------------------------
// K2: hilbert+X. blocks [0,256): 2048-pt FFT->filter->iFFT.
//     blocks [256,384): jac region H (108 MiB).
//     blocks [384,512): X role — x_hat = z @ W_dec^T + b_dec.
// ---------------------------------------------------------------------------
__global__ __launch_bounds__(1024) void hilbert_kernel(
    const float* __restrict__ W_enc,
    const float* __restrict__ W_dec, const float* __restrict__ b_dec,
    const float* __restrict__ z, float* __restrict__ out)
{
    __shared__ float2 bufA[2048];
    __shared__ float2 bufB[2048];
    const int tid = threadIdx.x;
    const int bb  = blockIdx.x;

    if (bb >= 384) {
        // ---- X role: rows [g*256, +256), 8 row-groups x 128 cols ----
        const int g   = bb - 384;
        const int col = tid & 127;
        const int rg  = tid >> 7;         // 0..7
        const float4* wd = (const float4*)W_dec;
        float4 w0 = wd[col * 4 + 0];
        float4 w1 = wd[col * 4 + 1];
        float4 w2 = wd[col * 4 + 2];
        float4 w3 = wd[col * 4 + 3];
        float  bd = b_dec[col];
        const int rbase = g * 256 + rg * 32;
#pragma unroll 4
        for (int rr = 0; rr < 32; rr++) {
            const float4* zr = (const float4*)(z + (size_t)(rbase + rr) * LDIM);
            float4 z0 = __ldg(zr + 0), z1 = __ldg(zr + 1);
            float4 z2 = __ldg(zr + 2), z3 = __ldg(zr + 3);
            float v = bd;
            v = fmaf(z0.x, w0.x, v); v = fmaf(z0.y, w0.y, v);
            v = fmaf(z0.z, w0.z, v); v = fmaf(z0.w, w0.w, v);
            v = fmaf(z1.x, w1.x, v); v = fmaf(z1.y, w1.y, v);
            v = fmaf(z1.z, w1.z, v); v = fmaf(z1.w, w1.w, v);
            v = fmaf(z2.x, w2.x, v); v = fmaf(z2.y, w2.y, v);
            v = fmaf(z2.z, w2.z, v); v = fmaf(z2.w, w2.w, v);
            v = fmaf(z3.x, w3.x, v); v = fmaf(z3.y, w3.y, v);
            v = fmaf(z3.z, w3.z, v); v = fmaf(z3.w, w3.w, v);
            out[X_OFF + (size_t)(rbase + rr) * FDIM + col] = v;
        }
        return;
    }

    if (bb >= 256) {
        float4* tile = (float4*)bufA;
        const float4* we4 = (const float4*)W_enc;
        if (tid < 512) tile[tid] = we4[tid];
        __syncthreads();
        jac_store(out, tile, JAC_H_BEG, JAC_H_LEN, bb - 256, 128, tid, 1024);
        return;
    }

    const int seq = bb;
    const float* zp = g_zt + (size_t)seq * TDIM;
    bufA[tid]        = make_float2(zp[tid], 0.0f);
    bufA[tid + 1024] = make_float2(zp[tid + 1024], 0.0f);
    __syncthreads();

    float2* src = bufA;
    float2* dst = bufB;

#pragma unroll 1
    for (int p = 0; p < 11; p++) {                 // forward FFT
        const int   len  = 1 << p;
        const float coef = -3.14159265358979323846f / (float)len;
        const int j = tid;
        const int k = j & (len - 1);
        float2 a  = src[j];
        float2 b2 = src[j + 1024];
        float s, c;
        __sincosf(coef * (float)k, &s, &c);
        float2 wb = make_float2(c * b2.x - s * b2.y, c * b2.y + s * b2.x);
        const int base = 2 * (j - k) + k;
        dst[base]       = make_float2(a.x + wb.x, a.y + wb.y);
        dst[base + len] = make_float2(a.x - wb.x, a.y - wb.y);
        __syncthreads();
        float2* tsw = src; src = dst; dst = tsw;
    }

    {   // H filter: H[0]=0, H[1..1023]=2, H[1024..2047]=0
        float h0 = (tid >= 1) ? 2.0f : 0.0f;
        src[tid].x *= h0;  src[tid].y *= h0;
        src[tid + 1024].x = 0.0f; src[tid + 1024].y = 0.0f;
    }
    __syncthreads();

#pragma unroll 1
    for (int p = 0; p < 11; p++) {                 // inverse FFT
        const int   len  = 1 << p;
        const float coef = 3.14159265358979323846f / (float)len;
        const int j = tid;
        const int k = j & (len - 1);
        float2 a  = src[j];
        float2 b2 = src[j + 1024];
        float s, c;
        __sincosf(coef * (float)k, &s, &c);
        float2 wb = make_float2(c * b2.x - s * b2.y, c * b2.y + s * b2.x);
        const int base = 2 * (j - k) + k;
        dst[base]       = make_float2(a.x + wb.x, a.y + wb.y);
        dst[base + len] = make_float2(a.x - wb.x, a.y - wb.y);
        __syncthreads();
        float2* tsw = src; src = dst; dst = tsw;
    }

    const float scale = 1.0f / 2048.0f;
    const size_t ob = (size_t)seq * TDIM;
#pragma unroll
    for (int it = 0; it < 2; it++) {
        int t = tid + it * 1024;
        float re = src[t].x * scale;
        float im = src[t].y * scale;
        g_amp[ob + t] = sqrtf(re * re + im * im);
        g_ang[ob + t] = atan2f(im, re);
    }
}

// ---------------------------------------------------------------------------
// K3: fused (Y + jac), R12 structure. 1024 blocks x 256 thr, 3/SM; block bb
// owns one 32-row tile and jac slice [bb*6400, +6400). Wt/combo in smem.
// Y: warp = feature octant (broadcast weights, f32x2 FMA), lane = row.
// Reduce: 3-round tree reusing the f/combo region (dead after the Y loop).
// Block 1024: copy W_sindy, W_dec.
// ---------------------------------------------------------------------------
#define ADD2(dst, srcv) asm("add.rn.f32x2 %0,%0,%1;" : "+l"(dst) : "l"(srcv))

__global__ __launch_bounds__(256, 3) void fused_kernel(
    const float* __restrict__ W_enc,
    const float* __restrict__ W_dec,
    const float* __restrict__ W_sindy, const float* __restrict__ b_sindy,
    const float* __restrict__ z,       // z region of output blob [B,T,L]
    float* __restrict__ out)
{
    extern __shared__ float smem[];
    const int tid = threadIdx.x;
    const int bb  = blockIdx.x;

    if (bb == 1024) {
        const float4* ws4 = (const float4*)W_sindy;
        float4* o1 = (float4*)(out + WS_OFF);
        for (int i = tid; i < (LDIM * LIB) / 4; i += 256) o1[i] = ws4[i];
        const float4* wd4 = (const float4*)W_dec;
        float4* o2 = (float4*)(out + WD_OFF);
        for (int i = tid; i < (FDIM * LDIM) / 4; i += 256) o2[i] = wd4[i];
        return;
    }

    // ---- (1) jac slice: 6400 float4 per block (25/thread), fire-and-forget
    {
        const float4* we4 = (const float4*)W_enc;
        float4* jac4 = (float4*)(out + J_OFF);
        const size_t vbase = JAC_F_BEG + (size_t)bb * 6400 + tid;
#pragma unroll 5
        for (int k = 0; k < 25; k++) {
            size_t v = vbase + (size_t)k * 256;
            __stcs(&jac4[v], __ldg(&we4[v & 511]));
        }
    }

    // ---- (2) smem fill ----
    float* s_Wt = smem;                       // [1016][16]
    float* s_f  = smem + SM_F;                // [32][53]
    unsigned int* s_combo = (unsigned int*)(smem + SM_COMBO);
    {
        const float4* wt4 = (const float4*)g_Wt;
        float4* d4 = (float4*)s_Wt;
        for (int i = tid; i < (LIB * LDIM) / 4; i += 256) d4[i] = wt4[i];
        for (int i = tid; i < LIB; i += 256) s_combo[i] = g_combo[i];
    }

    const int u    = tid >> 5;        // warp id = feature octant
    const int lane = tid & 31;        // row within tile
    const int row  = bb * 32 + lane;
    const int b    = row >> 11;
    const int tt   = row & 2047;
    float* f = s_f + lane * 53;
#pragma unroll
    for (int m = 0; m < 6; m++) {
        int idx = u * 6 + m;              // 0..47
        float val;
        if (idx < 16)      val = z[(size_t)row * LDIM + idx];
        else if (idx < 32) val = g_amp[((size_t)(b * 16 + idx - 16)) * TDIM + tt];
        else               val = g_ang[((size_t)(b * 16 + idx - 32)) * TDIM + tt];
        f[idx] = val;
    }
    if (u == 0) { f[48] = 1.0f; f[49] = 1.0f; f[50] = 1.0f; f[51] = 1.0f; f[52] = 1.0f; }
    __syncthreads();

    // ---- (3) Y: warp u walks d = u*127..u*127+126, packed f32x2 FMA ----
    unsigned long long A0 = 0, A1 = 0, A2 = 0, A3 = 0,
                       A4 = 0, A5 = 0, A6 = 0, A7 = 0;
    int d = u * 127;
#pragma unroll 2
    for (int s = 0; s < 127; s++, d++) {
        unsigned int c = s_combo[d];                       // broadcast
        float v = f[c & 63u] * f[(c >> 8) & 63u] * f[(c >> 16) & 63u];
        unsigned long long pk;
        asm("mov.b64 %0,{%1,%1};" : "=l"(pk) : "r"(__float_as_uint(v)));
        const ulonglong2* w2 = (const ulonglong2*)(s_Wt + (d << 4)); // broadcast
        ulonglong2 p0 = w2[0], p1 = w2[1];
        asm("fma.rn.f32x2 %0,%1,%2,%0;" : "+l"(A0) : "l"(pk), "l"(p0.x));
        asm("fma.rn.f32x2 %0,%1,%2,%0;" : "+l"(A1) : "l"(pk), "l"(p0.y));
        asm("fma.rn.f32x2 %0,%1,%2,%0;" : "+l"(A2) : "l"(pk), "l"(p1.x));
        asm("fma.rn.f32x2 %0,%1,%2,%0;" : "+l"(A3) : "l"(pk), "l"(p1.y));
        ulonglong2 p2 = w2[2], p3 = w2[3];
        asm("fma.rn.f32x2 %0,%1,%2,%0;" : "+l"(A4) : "l"(pk), "l"(p2.x));
        asm("fma.rn.f32x2 %0,%1,%2,%0;" : "+l"(A5) : "l"(pk), "l"(p2.y));
        asm("fma.rn.f32x2 %0,%1,%2,%0;" : "+l"(A6) : "l"(pk), "l"(p3.x));
        asm("fma.rn.f32x2 %0,%1,%2,%0;" : "+l"(A7) : "l"(pk), "l"(p3.y));
    }
    __syncthreads();    // f/combo dead; region becomes reduce buffer

    float* s_red = smem + SM_RED;

    // round 1: warps 4-7 store, warps 0-3 add
    if (u >= 4) {
        ulonglong2* r2 = (ulonglong2*)(s_red + ((u - 4) * 32 + lane) * 16);
        ulonglong2 q;
        q.x = A0; q.y = A1; r2[0] = q;
        q.x = A2; q.y = A3; r2[1] = q;
        q.x = A4; q.y = A5; r2[2] = q;
        q.x = A6; q.y = A7; r2[3] = q;
    }
    __syncthreads();
    if (u < 4) {
        const ulonglong2* r2 = (const ulonglong2*)(s_red + (u * 32 + lane) * 16);
        ulonglong2 q0 = r2[0], q1 = r2[1], q2 = r2[2], q3 = r2[3];
        ADD2(A0, q0.x); ADD2(A1, q0.y); ADD2(A2, q1.x); ADD2(A3, q1.y);
        ADD2(A4, q2.x); ADD2(A5, q2.y); ADD2(A6, q3.x); ADD2(A7, q3.y);
    }
    __syncthreads();
    // round 2: warps 2-3 store, warps 0-1 add
    if (u == 2 || u == 3) {
        ulonglong2* r2 = (ulonglong2*)(s_red + ((u - 2) * 32 + lane) * 16);
        ulonglong2 q;
        q.x = A0; q.y = A1; r2[0] = q;
        q.x = A2; q.y = A3; r2[1] = q;
        q.x = A4; q.y = A5; r2[2] = q;
        q.x = A6; q.y = A7; r2[3] = q;
    }
    __syncthreads();
    if (u < 2) {
        const ulonglong2* r2 = (const ulonglong2*)(s_red + (u * 32 + lane) * 16);
        ulonglong2 q0 = r2[0], q1 = r2[1], q2 = r2[2], q3 = r2[3];
        ADD2(A0, q0.x); ADD2(A1, q0.y); ADD2(A2, q1.x); ADD2(A3, q1.y);
        ADD2(A4, q2.x); ADD2(A5, q2.y); ADD2(A6, q3.x); ADD2(A7, q3.y);
    }
    __syncthreads();
    // round 3: warp 1 stores, warp 0 adds + bias + output
    if (u == 1) {
        ulonglong2* r2 = (ulonglong2*)(s_red + lane * 16);
        ulonglong2 q;
        q.x = A0; q.y = A1; r2[0] = q;
        q.x = A2; q.y = A3; r2[1] = q;
        q.x = A4; q.y = A5; r2[2] = q;
        q.x = A6; q.y = A7; r2[3] = q;
    }
    __syncthreads();
    if (u == 0) {
        const ulonglong2* r2 = (const ulonglong2*)(s_red + lane * 16);
        ulonglong2 q0 = r2[0], q1 = r2[1], q2 = r2[2], q3 = r2[3];
        ADD2(A0, q0.x); ADD2(A1, q0.y); ADD2(A2, q1.x); ADD2(A3, q1.y);
        ADD2(A4, q2.x); ADD2(A5, q2.y); ADD2(A6, q3.x); ADD2(A7, q3.y);

        const float4* bs4 = (const float4*)b_sindy;
        float4 b0 = __ldg(bs4 + 0), b1 = __ldg(bs4 + 1);
        float4 b2 = __ldg(bs4 + 2), b3 = __ldg(bs4 + 3);
        float2 v0 = *(float2*)&A0, v1 = *(float2*)&A1;
        float2 v2 = *(float2*)&A2, v3 = *(float2*)&A3;
        float2 v4 = *(float2*)&A4, v5 = *(float2*)&A5;
        float2 v6 = *(float2*)&A6, v7 = *(float2*)&A7;
        float4* yo = (float4*)(out + Y_OFF + (size_t)row * LDIM);
        yo[0] = make_float4(v0.x + b0.x, v0.y + b0.y, v1.x + b0.z, v1.y + b0.w);
        yo[1] = make_float4(v2.x + b1.x, v2.y + b1.y, v3.x + b1.z, v3.y + b1.w);
        yo[2] = make_float4(v4.x + b2.x, v4.y + b2.y, v5.x + b2.z, v5.y + b2.w);
        yo[3] = make_float4(v6.x + b3.x, v6.y + b3.y, v7.x + b3.z, v7.y + b3.w);
    }
}

// ---------------------------------------------------------------------------
extern "C" void kernel_launch(void* const* d_in, const int* in_sizes, int n_in,
                              void* d_out, int out_size)
{
    const float* x       = (const float*)d_in[0];
    const float* W_enc   = (const float*)d_in[1];
    const float* b_enc   = (const float*)d_in[2];
    const float* W_dec   = (const float*)d_in[3];
    const float* b_dec   = (const float*)d_in[4];
    const float* W_sindy = (const float*)d_in[5];
    const float* b_sindy = (const float*)d_in[6];
    float* out = (float*)d_out;

    float* z_out = out + Z_OFF;

    encoder_kernel<<<513, 256>>>(x, W_enc, b_enc, W_sindy, z_out, out);
    hilbert_kernel<<<512, 1024>>>(W_enc, W_dec, b_dec, z_out, out);

    static int smem_set = 0;
    if (!smem_set) {
        cudaFuncSetAttribute(fused_kernel,
                             cudaFuncAttributeMaxDynamicSharedMemorySize,
                             FUSED_SMEM_BYTES);
        smem_set = 1;
    }
    fused_kernel<<<1025, 256, FUSED_SMEM_BYTES>>>(
        W_enc, W_dec, W_sindy, b_sindy, z_out, out);
}